// round 11
// baseline (speedup 1.0000x reference)
#include <cuda_runtime.h>
#include <cuda_bf16.h>

// Focal cross-entropy sum over N rows, 2 classes — single fused kernel.
//   d = p1-p0 ; ex = e^d ; u = 1+ex ; lse = log u ; q0 = 1/u ; q1 = ex/u
//   loss_i = oh0*lse*q1^2 + oh1*(lse-d)*q0^2
//   t = gold>=0.5 ; oh1 = t?0.25:0 ; oh0 = (1-oh1)*0.75
//
// R11: software pipelining (prefetch depth 1). In R3..R10 loads were only
// outstanding while the warp stalled at the first consumer; during the
// ~70-instr compute phase each warp had 0 bytes in flight (issue=50%,
// DRAM=69%, occ=90% — latency gap). Now each iter prefetches the next
// 48B tile into registers BEFORE computing the current one, keeping 4 loads
// in flight through compute. __launch_bounds__(512,3) caps regs (~40) ->
// 48 warps/SM.

static constexpr int BLOCKS  = 1024;
static constexpr int THREADS = 512;

__device__ float g_partials[BLOCKS];
__device__ unsigned int g_ticket = 0;   // returns to 0 every run -> graph-replay safe

__device__ __forceinline__ float fast_rcp(float x) {
    float r;
    asm("rcp.approx.f32 %0, %1;" : "=f"(r) : "f"(x));
    return r;
}

__device__ __forceinline__ float row_loss(float p0, float p1, float gold) {
    float d  = p1 - p0;
    float ex = __expf(d);            // safe: |d| <= ~9 for N(0,2) data; overflow at 88
    float u  = 1.0f + ex;
    float lse = __logf(u);           // log(1+e^d)
    float q0 = fast_rcp(u);          // prb0
    float q1 = ex * q0;              // prb1
    bool t = (gold >= 0.5f);
    float oh1 = t ? 0.25f   : 0.0f;
    float oh0 = t ? 0.5625f : 0.75f; // (1 - oh1) * 0.75
    // loss = oh0*lse*prb1^2 + oh1*(lse-d)*prb0^2
    return oh0 * lse * q1 * q1 + oh1 * (lse - d) * q0 * q0;
}

__global__ void __launch_bounds__(THREADS, 3)
focal_sum_fused(const float* __restrict__ pred,
                const float* __restrict__ gold,
                float* __restrict__ out,
                int n_rows) {
    const float4* pred4 = reinterpret_cast<const float4*>(pred);  // 1 float4 = 2 rows
    const float2* gold2 = reinterpret_cast<const float2*>(gold);  // 1 float2 = 2 rows

    int n_pairs = n_rows >> 1;            // row-pair units
    const int TILE   = THREADS * 2;       // pairs per block per iter
    const int STRIDE = BLOCKS * TILE;     // pairs per grid iter

    float acc = 0.0f;

    if (n_pairs % STRIDE == 0) {
        // ---- fast path (benchmark shape: exactly n_pairs/STRIDE iterations) ----
        int n_iter = n_pairs / STRIDE;
        int idx = blockIdx.x * TILE + threadIdx.x;

        // prologue: load tile 0
        float4 pA = pred4[idx];
        float4 pB = pred4[idx + THREADS];
        float2 gA = gold2[idx];
        float2 gB = gold2[idx + THREADS];

        for (int it = 0; it < n_iter - 1; it++) {
            int nidx = idx + STRIDE;
            // prefetch next tile — loads in flight during the compute below
            float4 npA = pred4[nidx];
            float4 npB = pred4[nidx + THREADS];
            float2 ngA = gold2[nidx];
            float2 ngB = gold2[nidx + THREADS];

            acc += row_loss(pA.x, pA.y, gA.x);
            acc += row_loss(pA.z, pA.w, gA.y);
            acc += row_loss(pB.x, pB.y, gB.x);
            acc += row_loss(pB.z, pB.w, gB.y);

            pA = npA; pB = npB; gA = ngA; gB = ngB;
            idx = nidx;
        }
        // epilogue: compute last tile
        acc += row_loss(pA.x, pA.y, gA.x);
        acc += row_loss(pA.z, pA.w, gA.y);
        acc += row_loss(pB.x, pB.y, gB.x);
        acc += row_loss(pB.z, pB.w, gB.y);
    } else {
        // ---- generic path (any shape) ----
        for (int base = blockIdx.x * TILE + threadIdx.x; base < n_pairs; base += STRIDE) {
            int i1 = base + THREADS;
            float4 pA = pred4[base];
            float2 gA = gold2[base];
            if (i1 < n_pairs) {
                float4 pB = pred4[i1];
                float2 gB = gold2[i1];
                acc += row_loss(pA.x, pA.y, gA.x);
                acc += row_loss(pA.z, pA.w, gA.y);
                acc += row_loss(pB.x, pB.y, gB.x);
                acc += row_loss(pB.z, pB.w, gB.y);
            } else {
                acc += row_loss(pA.x, pA.y, gA.x);
                acc += row_loss(pA.z, pA.w, gA.y);
            }
        }
        // Tail row (n_rows odd)
        if ((n_rows & 1) && blockIdx.x == 0 && threadIdx.x == 0) {
            int r = n_rows - 1;
            acc += row_loss(pred[2 * r], pred[2 * r + 1], gold[r]);
        }
    }

    // Block reduction
    #pragma unroll
    for (int off = 16; off > 0; off >>= 1)
        acc += __shfl_xor_sync(0xFFFFFFFFu, acc, off);

    __shared__ float warp_sums[THREADS / 32];
    __shared__ bool  is_last;
    int lane = threadIdx.x & 31;
    int wid  = threadIdx.x >> 5;
    if (lane == 0) warp_sums[wid] = acc;
    __syncthreads();

    if (wid == 0) {
        float v = (lane < THREADS / 32) ? warp_sums[lane] : 0.0f;
        #pragma unroll
        for (int off = 16; off > 0; off >>= 1)
            v += __shfl_xor_sync(0xFFFFFFFFu, v, off);
        if (lane == 0) {
            g_partials[blockIdx.x] = v;
            __threadfence();                         // make partial visible
            unsigned int t = atomicAdd(&g_ticket, 1u);
            is_last = (t == BLOCKS - 1);
        }
    }
    __syncthreads();

    // Last-arriving block performs the deterministic final reduction
    // (fixed summation order regardless of which block arrives last).
    if (is_last) {
        float v = 0.0f;
        for (int i = threadIdx.x; i < BLOCKS; i += THREADS)
            v += g_partials[i];

        #pragma unroll
        for (int off = 16; off > 0; off >>= 1)
            v += __shfl_xor_sync(0xFFFFFFFFu, v, off);
        if (lane == 0) warp_sums[wid] = v;
        __syncthreads();
        if (wid == 0) {
            float w = (lane < THREADS / 32) ? warp_sums[lane] : 0.0f;
            #pragma unroll
            for (int off = 16; off > 0; off >>= 1)
                w += __shfl_xor_sync(0xFFFFFFFFu, w, off);
            if (lane == 0) {
                out[0] = w;          // CORR = 1.0
                g_ticket = 0;        // reset for next graph replay
            }
        }
    }
}

extern "C" void kernel_launch(void* const* d_in, const int* in_sizes, int n_in,
                              void* d_out, int out_size) {
    const float* pred = (const float*)d_in[0];   // [N, 2] f32
    const float* gold = (const float*)d_in[1];   // [N]    f32
    int n_rows = in_sizes[1];

    focal_sum_fused<<<BLOCKS, THREADS>>>(pred, gold, (float*)d_out, n_rows);
}

// round 12
// speedup vs baseline: 1.1655x; 1.1655x over previous
#include <cuda_runtime.h>
#include <cuda_bf16.h>

// Focal cross-entropy sum over N rows, 2 classes — single fused kernel.
// Base-2 domain:  e = d*log2e ; ex = 2^e ; u = 1+ex ; L = lg2(u)
//   q0 = 1/u ; q1 = ex/u
//   per-row reduced loss:  A + t*(B/3 - A/4),  A = L*q1^2, B = (L-e)*q0^2
//   total = 0.75*ln2 * sum  (scale applied ONCE at the final write)
//   t = gold>=0.5
//
// R12: instruction-count cut (issue-coupled BW model: ~19 B/instr needs 55%
// issue to hit the DRAM roof; achievable is ~50%). FMA-pipe chain runs as
// packed f32x2 over the two rows of each float4 (PTX-only ops); MUFU scalar
// on halves; 0.75*ln2 factored out of the whole sum. Geometry/loop = R9.

static constexpr int BLOCKS  = 1024;
static constexpr int THREADS = 512;

__device__ float g_partials[BLOCKS];
__device__ unsigned int g_ticket = 0;   // returns to 0 every run -> graph-replay safe

// ---- packed f32x2 helpers (sm_100a) ----
typedef unsigned long long u64;
__device__ __forceinline__ u64 pk2(float lo, float hi) {
    u64 r; asm("mov.b64 %0, {%1, %2};" : "=l"(r) : "f"(lo), "f"(hi)); return r;
}
__device__ __forceinline__ void upk2(float& lo, float& hi, u64 v) {
    asm("mov.b64 {%0, %1}, %2;" : "=f"(lo), "=f"(hi) : "l"(v));
}
__device__ __forceinline__ u64 add2(u64 a, u64 b) {
    u64 r; asm("add.rn.f32x2 %0, %1, %2;" : "=l"(r) : "l"(a), "l"(b)); return r;
}
__device__ __forceinline__ u64 mul2(u64 a, u64 b) {
    u64 r; asm("mul.rn.f32x2 %0, %1, %2;" : "=l"(r) : "l"(a), "l"(b)); return r;
}
__device__ __forceinline__ u64 fma2(u64 a, u64 b, u64 c) {
    u64 r; asm("fma.rn.f32x2 %0, %1, %2, %3;" : "=l"(r) : "l"(a), "l"(b), "l"(c)); return r;
}
__device__ __forceinline__ float ex2f(float x){ float r; asm("ex2.approx.f32 %0, %1;" : "=f"(r) : "f"(x)); return r; }
__device__ __forceinline__ float lg2f(float x){ float r; asm("lg2.approx.f32 %0, %1;" : "=f"(r) : "f"(x)); return r; }
__device__ __forceinline__ float rcpf(float x){ float r; asm("rcp.approx.f32 %0, %1;" : "=f"(r) : "f"(x)); return r; }

static constexpr float L2E   = 1.4426950408889634f;  // log2(e)
static constexpr float SCALE = 0.75f * 0.6931471805599453f;  // 0.75*ln2

// Scalar reduced-domain row loss (tail path): A + t*(B/3 - A/4)
__device__ __forceinline__ float row_core(float p0, float p1, float gold) {
    float d  = p1 - p0;
    float e  = d * L2E;
    float ex = ex2f(e);
    float u  = 1.0f + ex;
    float L  = lg2f(u);
    float q0 = rcpf(u);
    float q1 = ex * q0;
    float A  = L * (q1 * q1);
    float B  = (L - e) * (q0 * q0);
    float C  = B * 0.33333334f - A * 0.25f;
    float t  = (gold >= 0.5f) ? 1.0f : 0.0f;
    return A + t * C;
}

// Packed 2-row body: rows (p.x,p.y) and (p.z,p.w), golds (g.x,g.y).
__device__ __forceinline__ void rows2_packed(float4 p, float2 g, u64& acc2,
                                             u64 KM1, u64 K13, u64 KM025) {
    float da = p.y - p.x,   db = p.w - p.z;
    float ea = da * L2E,    eb = db * L2E;
    float xa = ex2f(ea),    xb = ex2f(eb);
    float ua = 1.0f + xa,   ub = 1.0f + xb;
    float La = lg2f(ua),    Lb = lg2f(ub);
    float ra = rcpf(ua),    rb = rcpf(ub);

    u64 q0 = pk2(ra, rb);
    u64 ex = pk2(xa, xb);
    u64 L  = pk2(La, Lb);
    u64 e2 = pk2(ea, eb);

    u64 q1  = mul2(ex, q0);
    u64 q1s = mul2(q1, q1);
    u64 A   = mul2(L, q1s);
    u64 Le  = fma2(e2, KM1, L);          // L - e
    u64 q0s = mul2(q0, q0);
    u64 B   = mul2(Le, q0s);
    u64 C   = fma2(B, K13, mul2(A, KM025));   // B/3 - A/4

    float ta = (g.x >= 0.5f) ? 1.0f : 0.0f;
    float tb = (g.y >= 0.5f) ? 1.0f : 0.0f;
    u64 t2 = pk2(ta, tb);

    acc2 = add2(acc2, A);
    acc2 = fma2(C, t2, acc2);
}

__global__ void __launch_bounds__(THREADS)
focal_sum_fused(const float* __restrict__ pred,
                const float* __restrict__ gold,
                float* __restrict__ out,
                int n_rows) {
    const float4* pred4 = reinterpret_cast<const float4*>(pred);  // 1 float4 = 2 rows
    const float2* gold2 = reinterpret_cast<const float2*>(gold);  // 1 float2 = 2 rows

    int n_pairs = n_rows >> 1;            // row-pair units
    const int TILE   = THREADS * 2;       // pairs per block per iter
    const int STRIDE = BLOCKS * TILE;

    // packed constants (loop-invariant, hoisted by ptxas)
    const u64 KM1   = pk2(-1.0f, -1.0f);
    const u64 K13   = pk2(0.33333334f, 0.33333334f);
    const u64 KM025 = pk2(-0.25f, -0.25f);

    u64 acc2 = pk2(0.0f, 0.0f);
    float acc_s = 0.0f;   // tail-path scalar accumulator

    for (int base = blockIdx.x * TILE + threadIdx.x; base < n_pairs; base += STRIDE) {
        int i1 = base + THREADS;
        float4 pA = pred4[base];
        float2 gA = gold2[base];
        if (i1 < n_pairs) {
            float4 pB = pred4[i1];
            float2 gB = gold2[i1];
            rows2_packed(pA, gA, acc2, KM1, K13, KM025);
            rows2_packed(pB, gB, acc2, KM1, K13, KM025);
        } else {
            rows2_packed(pA, gA, acc2, KM1, K13, KM025);
        }
    }
    // Tail row (n_rows odd)
    if ((n_rows & 1) && blockIdx.x == 0 && threadIdx.x == 0) {
        int r = n_rows - 1;
        acc_s += row_core(pred[2 * r], pred[2 * r + 1], gold[r]);
    }

    float lo, hi;
    upk2(lo, hi, acc2);
    float acc = lo + hi + acc_s;

    // Block reduction
    #pragma unroll
    for (int off = 16; off > 0; off >>= 1)
        acc += __shfl_xor_sync(0xFFFFFFFFu, acc, off);

    __shared__ float warp_sums[THREADS / 32];
    __shared__ bool  is_last;
    int lane = threadIdx.x & 31;
    int wid  = threadIdx.x >> 5;
    if (lane == 0) warp_sums[wid] = acc;
    __syncthreads();

    if (wid == 0) {
        float v = (lane < THREADS / 32) ? warp_sums[lane] : 0.0f;
        #pragma unroll
        for (int off = 16; off > 0; off >>= 1)
            v += __shfl_xor_sync(0xFFFFFFFFu, v, off);
        if (lane == 0) {
            g_partials[blockIdx.x] = v;
            __threadfence();                         // make partial visible
            unsigned int t = atomicAdd(&g_ticket, 1u);
            is_last = (t == BLOCKS - 1);
        }
    }
    __syncthreads();

    // Last-arriving block performs the deterministic final reduction
    // (fixed summation order regardless of which block arrives last).
    if (is_last) {
        float v = 0.0f;
        for (int i = threadIdx.x; i < BLOCKS; i += THREADS)
            v += g_partials[i];

        #pragma unroll
        for (int off = 16; off > 0; off >>= 1)
            v += __shfl_xor_sync(0xFFFFFFFFu, v, off);
        if (lane == 0) warp_sums[wid] = v;
        __syncthreads();
        if (wid == 0) {
            float w = (lane < THREADS / 32) ? warp_sums[lane] : 0.0f;
            #pragma unroll
            for (int off = 16; off > 0; off >>= 1)
                w += __shfl_xor_sync(0xFFFFFFFFu, w, off);
            if (lane == 0) {
                out[0] = w * SCALE;  // 0.75*ln2, factored out of the whole sum
                g_ticket = 0;        // reset for next graph replay
            }
        }
    }
}

extern "C" void kernel_launch(void* const* d_in, const int* in_sizes, int n_in,
                              void* d_out, int out_size) {
    const float* pred = (const float*)d_in[0];   // [N, 2] f32
    const float* gold = (const float*)d_in[1];   // [N]    f32
    int n_rows = in_sizes[1];

    focal_sum_fused<<<BLOCKS, THREADS>>>(pred, gold, (float*)d_out, n_rows);
}